// round 11
// baseline (speedup 1.0000x reference)
#include <cuda_runtime.h>
#include <cuda_bf16.h>
#include <math.h>
#include <cstdint>

#define N_NODES 50000
#define N_PAD   50048            // 391 * 128
#define N_EDGES 800000
#define N_GRAPHS 256
#define D_IN 14
#define D_HID 256
#define SCAN_BLOCKS 196          // ceil(50000/256)
#define LIN1_BLOCKS 3125         // 50000/16
#define MISC_BLOCKS 304          // 256 (W2 split) + 48 (A pad)

// k_mma dynamic smem: 3 stages x (sA 128x40 + sB 128x40) bf16
#define MMA_STAGE_BYTES (128 * 40 * 2)
#define MMA_SMEM_BYTES  (6 * MMA_STAGE_BYTES)   // 61440

// ---- persistent device scratch (no dynamic allocation allowed) ----
__device__ float g_bufA[N_NODES * D_HID];                        // h2 (post-agg layer2)
__device__ float g_bufB[N_NODES * D_HID];                        // GEMM output h1@W2
__device__ __align__(16) __nv_bfloat16 g_Ah[(size_t)N_PAD * D_HID];  // h1 hi
__device__ __align__(16) __nv_bfloat16 g_Al[(size_t)N_PAD * D_HID];  // h1 lo
__device__ __align__(16) __nv_bfloat16 g_Bh[D_HID * D_HID];          // W2^T hi [n][k]
__device__ __align__(16) __nv_bfloat16 g_Bl[D_HID * D_HID];          // W2^T lo
__device__ float g_aggx[N_NODES * D_IN];
__device__ float g_dinv[N_NODES];
__device__ int   g_deg[N_NODES];        // zero at entry (static init + self-reset in scan1)
__device__ int   g_rowptr[N_NODES + 1];
__device__ int   g_cursor[N_NODES];
__device__ __align__(8) long long g_cw[N_EDGES];   // packed {int col, float wt}
__device__ int   g_bsum[256];
__device__ int   g_boff[256];
__device__ int   g_gptr[N_GRAPHS + 1];

__device__ __forceinline__ float selu_f(float x) {
    const float scale = 1.0507009873554805f;
    const float alpha = 1.6732632423543772f;
    return x > 0.f ? scale * x : scale * alpha * (expf(x) - 1.f);
}

__device__ __forceinline__ uint32_t smem_u32(const void* p) {
    uint32_t a;
    asm("{ .reg .u64 t; cvta.to.shared.u64 t, %1; cvt.u32.u64 %0, t; }" : "=r"(a) : "l"(p));
    return a;
}
__device__ __forceinline__ void ldsm4(uint32_t* r, uint32_t addr) {
    asm volatile("ldmatrix.sync.aligned.m8n8.x4.shared.b16 {%0,%1,%2,%3}, [%4];"
                 : "=r"(r[0]), "=r"(r[1]), "=r"(r[2]), "=r"(r[3]) : "r"(addr));
}
__device__ __forceinline__ void mma16816(float* d, const uint32_t* a, uint32_t b0, uint32_t b1) {
    asm volatile(
        "mma.sync.aligned.m16n8k16.row.col.f32.bf16.bf16.f32 "
        "{%0,%1,%2,%3}, {%4,%5,%6,%7}, {%8,%9}, {%0,%1,%2,%3};"
        : "+f"(d[0]), "+f"(d[1]), "+f"(d[2]), "+f"(d[3])
        : "r"(a[0]), "r"(a[1]), "r"(a[2]), "r"(a[3]), "r"(b0), "r"(b1));
}
__device__ __forceinline__ void cp16(uint32_t dst, const void* src) {
    asm volatile("cp.async.cg.shared.global [%0], [%1], 16;" :: "r"(dst), "l"(src));
}
__device__ __forceinline__ void cp_commit() {
    asm volatile("cp.async.commit_group;" ::: "memory");
}
template <int N> __device__ __forceinline__ void cp_wait() {
    asm volatile("cp.async.wait_group %0;" :: "n"(N) : "memory");
}

// ======================= CSR build =======================
__global__ void k_hist_edges(const int* __restrict__ ei) {
    int e = blockIdx.x * blockDim.x + threadIdx.x;
    if (e < N_EDGES) atomicAdd(&g_deg[ei[N_EDGES + e]], 1);
}

// block scan of degrees; also: dinv, and self-reset deg for next call
__global__ void k_scan1() {
    __shared__ int wsum[8];
    int b = blockIdx.x, t = threadIdx.x, lane = t & 31, w = t >> 5;
    int i = b * 256 + t;
    int v = 0;
    if (i < N_NODES) {
        v = g_deg[i];
        g_deg[i] = 0;                          // reset for next call's histogram
        g_dinv[i] = rsqrtf((float)(v + 1));    // +1 self loop
    }
    int x = v;
    #pragma unroll
    for (int o = 1; o < 32; o <<= 1) {
        int tv = __shfl_up_sync(0xffffffffu, x, o);
        if (lane >= o) x += tv;
    }
    if (lane == 31) wsum[w] = x;
    __syncthreads();
    if (w == 0) {
        int s = (lane < 8) ? wsum[lane] : 0;
        #pragma unroll
        for (int o = 1; o < 8; o <<= 1) {
            int tv = __shfl_up_sync(0xffffffffu, s, o);
            if (lane >= o) s += tv;
        }
        if (lane < 8) wsum[lane] = s;
    }
    __syncthreads();
    int offs = (w > 0) ? wsum[w - 1] : 0;
    if (i < N_NODES) g_rowptr[i] = x - v + offs;
    if (t == 0) g_bsum[b] = wsum[7];
}

__global__ void k_scan2() {
    __shared__ int wsum[8];
    int t = threadIdx.x, lane = t & 31, w = t >> 5;
    int v = (t < SCAN_BLOCKS) ? g_bsum[t] : 0;
    int x = v;
    #pragma unroll
    for (int o = 1; o < 32; o <<= 1) {
        int tv = __shfl_up_sync(0xffffffffu, x, o);
        if (lane >= o) x += tv;
    }
    if (lane == 31) wsum[w] = x;
    __syncthreads();
    if (w == 0) {
        int s = (lane < 8) ? wsum[lane] : 0;
        #pragma unroll
        for (int o = 1; o < 8; o <<= 1) {
            int tv = __shfl_up_sync(0xffffffffu, s, o);
            if (lane >= o) s += tv;
        }
        if (lane < 8) wsum[lane] = s;
    }
    __syncthreads();
    int offs = (w > 0) ? wsum[w - 1] : 0;
    g_boff[t] = x - v + offs;
    if (t == 0) g_rowptr[N_NODES] = N_EDGES;
}

// rowptr finalize + cursor init + graph-pointer boundary detection (batch is sorted)
__global__ void k_scan3(const int* __restrict__ batch) {
    int i = blockIdx.x * blockDim.x + threadIdx.x;
    if (i < N_NODES) {
        int r = g_rowptr[i] + g_boff[i >> 8];
        g_rowptr[i] = r;
        g_cursor[i] = r;
        int b = batch[i];
        int prev = (i == 0) ? -1 : batch[i - 1];
        for (int g = prev + 1; g <= b; g++) g_gptr[g] = i;
        if (i == N_NODES - 1)
            for (int g = b + 1; g <= N_GRAPHS; g++) g_gptr[g] = N_NODES;
    }
}

// fill CSR: packed {col, wt} single 8B scatter per edge
__global__ void k_fill(const int* __restrict__ ei) {
    int e = blockIdx.x * blockDim.x + threadIdx.x;
    if (e < N_EDGES) {
        int s = ei[e];
        int d = ei[N_EDGES + e];
        int p = atomicAdd(&g_cursor[d], 1);
        float w = g_dinv[s] * g_dinv[d];
        long long pk = (long long)(unsigned int)s |
                       ((long long)(unsigned int)__float_as_int(w) << 32);
        g_cw[p] = pk;
    }
}

// ---- layer-1 aggregation on RAW 14-dim input (agg commutes with W1) ----
__global__ void k_agg14(const float* __restrict__ x) {
    int warp = (blockIdx.x * blockDim.x + threadIdx.x) >> 5;
    int lane = threadIdx.x & 31;
    if (warp >= N_NODES) return;
    int n = warp;
    int half = lane >> 4;
    int f = lane & 15;
    float acc = 0.f;
    int e0 = g_rowptr[n], e1 = g_rowptr[n + 1];
    for (int i = e0 + half; i < e1; i += 2) {
        long long pk = __ldg(&g_cw[i]);
        int s = (int)(unsigned int)pk;
        float w = __int_as_float((int)(pk >> 32));
        if (f < D_IN) acc += x[(size_t)s * D_IN + f] * w;
    }
    if (half == 0 && f < D_IN) {
        float dn = g_dinv[n];
        acc += x[(size_t)n * D_IN + f] * dn * dn;
    }
    acc += __shfl_down_sync(0xffffffffu, acc, 16);
    if (half == 0 && f < D_IN) g_aggx[(size_t)n * D_IN + f] = acc;
}

// ---- layer-1 transform (blocks < LIN1_BLOCKS) + W2 split / A pad (blocks >=) ----
__global__ void k_lin1(const float* __restrict__ W1, const float* __restrict__ b1,
                       const float* __restrict__ W2) {
    int blk = blockIdx.x, tid = threadIdx.x;
    if (blk >= LIN1_BLOCKS) {
        int mb = blk - LIN1_BLOCKS;
        if (mb < 256) {
            int i = mb * 256 + tid;        // 65536
            int k = i >> 8, n = i & 255;
            float w = W2[i];
            __nv_bfloat16 wh = __float2bfloat16(w);
            float rem = w - __bfloat162float(wh);
            g_Bh[n * D_HID + k] = wh;
            g_Bl[n * D_HID + k] = __float2bfloat16(rem);
        } else {
            int i = (mb - 256) * 256 + tid;    // 48*256
            int r = N_NODES + (i >> 8), c = i & 255;
            g_Ah[(size_t)r * D_HID + c] = __float2bfloat16(0.f);
            g_Al[(size_t)r * D_HID + c] = __float2bfloat16(0.f);
        }
        return;
    }
    __shared__ float sW[D_IN * D_HID];
    __shared__ float sx[16 * D_IN];
    for (int i = tid; i < D_IN * D_HID; i += 256) sW[i] = W1[i];
    float bb = b1[tid];
    int n0 = blk * 16;
    int cnt = min(16, N_NODES - n0);
    for (int i = tid; i < cnt * D_IN; i += 256) sx[i] = g_aggx[(size_t)n0 * D_IN + i];
    __syncthreads();
    for (int r = 0; r < cnt; r++) {
        float acc = bb;
        #pragma unroll
        for (int k = 0; k < D_IN; k++) acc += sx[r * D_IN + k] * sW[k * D_HID + tid];
        float h = selu_f(acc);
        __nv_bfloat16 hh = __float2bfloat16(h);
        float rem = h - __bfloat162float(hh);
        size_t idx = (size_t)(n0 + r) * D_HID + tid;
        g_Ah[idx] = hh;
        g_Al[idx] = __float2bfloat16(rem);
    }
}

// ======================= split-bf16 HMMA GEMM (3-stage cp.async ring, dyn smem) =======
// Logical K=768: [0,256)=Ah*Bh, [256,512)=Al*Bh, [512,768)=Ah*Bl (single fp32 accum chain)
__global__ void __launch_bounds__(256, 2) k_mma() {
    extern __shared__ __align__(16) char dyn[];
    int tid = threadIdx.x;
    int lane = tid & 31, wid = tid >> 5;
    int warp_m = wid >> 2, warp_n = wid & 3;    // 2 x 4 warps, warp tile 64x32
    int bm = blockIdx.x * 128;
    int bn = blockIdx.y * 128;

    float acc[4][4][4];
    #pragma unroll
    for (int i = 0; i < 4; i++)
        #pragma unroll
        for (int j = 0; j < 4; j++)
            #pragma unroll
            for (int k = 0; k < 4; k++) acc[i][j][k] = 0.f;

    int lrow = tid >> 1;            // 0..127
    int lc4  = (tid & 1) * 2;       // uint4 index within 32-elem row chunk

    uint32_t base = smem_u32(dyn);
    uint32_t aB[3] = { base,                       base + MMA_STAGE_BYTES,
                       base + 2 * MMA_STAGE_BYTES };
    uint32_t bB[3] = { base + 3 * MMA_STAGE_BYTES, base + 4 * MMA_STAGE_BYTES,
                       base + 5 * MMA_STAGE_BYTES };
    int tmat = lane >> 3, trow = lane & 7;

    auto src_of = [&](int ch, const __nv_bfloat16*& Asrc, const __nv_bfloat16*& Bsrc) {
        int kg = ch * 32;
        if (kg < 256)      { Asrc = g_Ah + kg;         Bsrc = g_Bh + kg; }
        else if (kg < 512) { Asrc = g_Al + (kg - 256); Bsrc = g_Bh + (kg - 256); }
        else               { Asrc = g_Ah + (kg - 512); Bsrc = g_Bl + (kg - 512); }
    };
    auto issue = [&](int ch, int buf) {
        const __nv_bfloat16 *Asrc, *Bsrc;
        src_of(ch, Asrc, Bsrc);
        const uint4* ap = (const uint4*)(Asrc + (size_t)(bm + lrow) * D_HID);
        const uint4* bp = (const uint4*)(Bsrc + (size_t)(bn + lrow) * D_HID);
        uint32_t ad = aB[buf] + (lrow * 40 + lc4 * 8) * 2;
        uint32_t bd = bB[buf] + (lrow * 40 + lc4 * 8) * 2;
        cp16(ad,      ap + lc4);
        cp16(ad + 16, ap + lc4 + 1);
        cp16(bd,      bp + lc4);
        cp16(bd + 16, bp + lc4 + 1);
        cp_commit();
    };

    issue(0, 0);
    issue(1, 1);
    for (int ch = 0; ch < 24; ch++) {
        int cur = ch % 3;
        if (ch + 2 < 24) {
            issue(ch + 2, (ch + 2) % 3);
            cp_wait<2>();
        } else if (ch + 1 < 24) {
            cp_wait<1>();
        } else {
            cp_wait<0>();
        }
        __syncthreads();
        #pragma unroll
        for (int ks = 0; ks < 2; ks++) {
            uint32_t a[4][4], b[2][4];
            #pragma unroll
            for (int mt = 0; mt < 4; mt++) {
                int row = warp_m * 64 + mt * 16 + trow + (tmat & 1) * 8;
                int col = ks * 16 + (tmat >> 1) * 8;
                ldsm4(a[mt], aB[cur] + (row * 40 + col) * 2);
            }
            #pragma unroll
            for (int np = 0; np < 2; np++) {
                int row = warp_n * 32 + np * 16 + trow + (tmat >> 1) * 8;
                int col = ks * 16 + (tmat & 1) * 8;
                ldsm4(b[np], bB[cur] + (row * 40 + col) * 2);
            }
            #pragma unroll
            for (int mt = 0; mt < 4; mt++)
                #pragma unroll
                for (int nt = 0; nt < 4; nt++)
                    mma16816(acc[mt][nt], a[mt],
                             b[nt >> 1][(nt & 1) * 2], b[nt >> 1][(nt & 1) * 2 + 1]);
        }
        __syncthreads();
    }

    int gid = lane >> 2, tig = lane & 3;
    #pragma unroll
    for (int mt = 0; mt < 4; mt++) {
        #pragma unroll
        for (int nt = 0; nt < 4; nt++) {
            int r0 = bm + warp_m * 64 + mt * 16 + gid;
            int c  = bn + warp_n * 32 + nt * 8 + tig * 2;
            if (r0 < N_NODES)
                *(float2*)&g_bufB[(size_t)r0 * D_HID + c] =
                    make_float2(acc[mt][nt][0], acc[mt][nt][1]);
            int r1 = r0 + 8;
            if (r1 < N_NODES)
                *(float2*)&g_bufB[(size_t)r1 * D_HID + c] =
                    make_float2(acc[mt][nt][2], acc[mt][nt][3]);
        }
    }
}

// ---- layer-2 aggregation: g_bufA[n] = selu( agg(g_bufB) + b2 ) ----
// 128 threads = 2 nodes x 64 threads, float4 per thread, packed (col,wt) reads
__global__ void k_aggregate(const float* __restrict__ bias) {
    int tid = threadIdx.x;
    int n = blockIdx.x * 2 + (tid >> 6);
    int f = (tid & 63) * 4;
    if (n >= N_NODES) return;
    float dn = g_dinv[n];
    float sw = dn * dn;
    float4 sv = *(const float4*)&g_bufB[(size_t)n * D_HID + f];
    float4 accA = make_float4(sv.x * sw, sv.y * sw, sv.z * sw, sv.w * sw);
    float4 accB = make_float4(0.f, 0.f, 0.f, 0.f);
    int i = g_rowptr[n], e1 = g_rowptr[n + 1];
    for (; i + 4 <= e1; i += 4) {
        long long p0 = __ldg(&g_cw[i]);
        long long p1 = __ldg(&g_cw[i + 1]);
        long long p2 = __ldg(&g_cw[i + 2]);
        long long p3 = __ldg(&g_cw[i + 3]);
        int s0 = (int)(unsigned int)p0; float w0 = __int_as_float((int)(p0 >> 32));
        int s1 = (int)(unsigned int)p1; float w1 = __int_as_float((int)(p1 >> 32));
        int s2 = (int)(unsigned int)p2; float w2 = __int_as_float((int)(p2 >> 32));
        int s3 = (int)(unsigned int)p3; float w3 = __int_as_float((int)(p3 >> 32));
        float4 v0 = *(const float4*)&g_bufB[(size_t)s0 * D_HID + f];
        float4 v1 = *(const float4*)&g_bufB[(size_t)s1 * D_HID + f];
        float4 v2 = *(const float4*)&g_bufB[(size_t)s2 * D_HID + f];
        float4 v3 = *(const float4*)&g_bufB[(size_t)s3 * D_HID + f];
        accA.x += v0.x * w0; accA.y += v0.y * w0; accA.z += v0.z * w0; accA.w += v0.w * w0;
        accB.x += v1.x * w1; accB.y += v1.y * w1; accB.z += v1.z * w1; accB.w += v1.w * w1;
        accA.x += v2.x * w2; accA.y += v2.y * w2; accA.z += v2.z * w2; accA.w += v2.w * w2;
        accB.x += v3.x * w3; accB.y += v3.y * w3; accB.z += v3.z * w3; accB.w += v3.w * w3;
    }
    for (; i < e1; i++) {
        long long pk = __ldg(&g_cw[i]);
        int s = (int)(unsigned int)pk;
        float w = __int_as_float((int)(pk >> 32));
        float4 v = *(const float4*)&g_bufB[(size_t)s * D_HID + f];
        accA.x += v.x * w; accA.y += v.y * w; accA.z += v.z * w; accA.w += v.w * w;
    }
    const float4 bb = *(const float4*)&bias[f];
    float4 o;
    o.x = selu_f(accA.x + accB.x + bb.x);
    o.y = selu_f(accA.y + accB.y + bb.y);
    o.z = selu_f(accA.z + accB.z + bb.z);
    o.w = selu_f(accA.w + accB.w + bb.w);
    *(float4*)&g_bufA[(size_t)n * D_HID + f] = o;
}

// ---- fused head ----
__global__ void k_head(const float* __restrict__ fc1w, const float* __restrict__ fc1b,
                       const float* __restrict__ fc2w, const float* __restrict__ fc2b,
                       float* __restrict__ out) {
    __shared__ float sp[D_HID];
    __shared__ float h1[128];
    __shared__ float sl[2];
    int g = blockIdx.x, tid = threadIdx.x;
    int s = g_gptr[g], e = g_gptr[g + 1];
    float acc = 0.f;
    int n = s;
    for (; n + 4 <= e; n += 4) {
        float v0 = g_bufA[(size_t)(n + 0) * D_HID + tid];
        float v1 = g_bufA[(size_t)(n + 1) * D_HID + tid];
        float v2 = g_bufA[(size_t)(n + 2) * D_HID + tid];
        float v3 = g_bufA[(size_t)(n + 3) * D_HID + tid];
        acc += (v0 + v1) + (v2 + v3);
    }
    for (; n < e; n++) acc += g_bufA[(size_t)n * D_HID + tid];
    float c = fmaxf((float)(e - s), 1.f);
    sp[tid] = selu_f(acc / c);
    __syncthreads();
    if (tid < 128) {
        float a = fc1b[tid];
        #pragma unroll 8
        for (int k = 0; k < D_HID; k++) a += sp[k] * fc1w[k * 128 + tid];
        h1[tid] = selu_f(a);
    }
    __syncthreads();
    if (tid < 64) {
        int cc = tid >> 5, lane = tid & 31;
        float p = 0.f;
        for (int k = lane; k < 128; k += 32) p += h1[k] * fc2w[k * 2 + cc];
        #pragma unroll
        for (int o = 16; o; o >>= 1) p += __shfl_down_sync(0xffffffffu, p, o);
        if (lane == 0) sl[cc] = p + fc2b[cc];
    }
    __syncthreads();
    if (tid < 2) {
        float l0 = sl[0], l1 = sl[1];
        float m = fmaxf(l0, l1);
        float lse = m + logf(expf(l0 - m) + expf(l1 - m));
        out[g * 2 + tid] = sl[tid] - lse;
    }
}

extern "C" void kernel_launch(void* const* d_in, const int* in_sizes, int n_in,
                              void* d_out, int out_size) {
    const float* x     = (const float*)d_in[0];
    const int*   ei    = (const int*)d_in[1];
    const int*   batch = (const int*)d_in[2];
    const float* W1    = (const float*)d_in[3];
    const float* b1    = (const float*)d_in[4];
    const float* W2    = (const float*)d_in[5];
    const float* b2    = (const float*)d_in[6];
    const float* fc1w  = (const float*)d_in[7];
    const float* fc1b  = (const float*)d_in[8];
    const float* fc2w  = (const float*)d_in[9];
    const float* fc2b  = (const float*)d_in[10];
    float* out = (float*)d_out;

    cudaFuncSetAttribute(k_mma, cudaFuncAttributeMaxDynamicSharedMemorySize, MMA_SMEM_BYTES);

    // CSR + normalization build (g_deg is zero at entry: static init + scan1 self-reset)
    k_hist_edges<<<(N_EDGES + 255) / 256, 256>>>(ei);
    k_scan1<<<SCAN_BLOCKS, 256>>>();
    k_scan2<<<1, 256>>>();
    k_scan3<<<(N_NODES + 255) / 256, 256>>>(batch);
    k_fill<<<(N_EDGES + 255) / 256, 256>>>(ei);

    // layer 1: aggregate raw input, transform + bf16 hi/lo split (+ fused W2 split/pad)
    k_agg14<<<(N_NODES * 32 + 127) / 128, 128>>>(x);
    k_lin1<<<LIN1_BLOCKS + MISC_BLOCKS, 256>>>(W1, b1, W2);

    // layer 2: HMMA split-bf16 GEMM (3-stage cp.async, dyn smem), then aggregate
    dim3 gmma(N_PAD / 128, 2);
    k_mma<<<gmma, 256, MMA_SMEM_BYTES>>>();
    k_aggregate<<<N_NODES / 2, 128>>>(b2);

    // head
    k_head<<<N_GRAPHS, 256>>>(fc1w, fc1b, fc2w, fc2b, out);
}

// round 12
// speedup vs baseline: 1.0429x; 1.0429x over previous
#include <cuda_runtime.h>
#include <cuda_bf16.h>
#include <cuda_fp16.h>
#include <math.h>
#include <cstdint>

#define N_NODES 50000
#define N_PAD   50048            // 391 * 128
#define N_EDGES 800000
#define N_GRAPHS 256
#define D_IN 14
#define D_HID 256
#define SCAN_BLOCKS 196          // ceil(50000/256)
#define LIN1_BLOCKS 3125         // 50000/16
#define MISC_BLOCKS 304          // 256 (W2 split) + 48 (A pad)

// k_mma dynamic smem: 3 stages x (sA 128x40 + sB 128x40) bf16
#define MMA_STAGE_BYTES (128 * 40 * 2)
#define MMA_SMEM_BYTES  (6 * MMA_STAGE_BYTES)   // 61440

// ---- persistent device scratch (no dynamic allocation allowed) ----
__device__ float  g_bufA[N_NODES * D_HID];                       // h2 (post-agg layer2)
__device__ __align__(16) __half g_h2[(size_t)N_NODES * D_HID];   // GEMM output h1@W2 (fp16)
__device__ __align__(16) __nv_bfloat16 g_Ah[(size_t)N_PAD * D_HID];  // h1 hi
__device__ __align__(16) __nv_bfloat16 g_Al[(size_t)N_PAD * D_HID];  // h1 lo
__device__ __align__(16) __nv_bfloat16 g_Bh[D_HID * D_HID];          // W2^T hi [n][k]
__device__ __align__(16) __nv_bfloat16 g_Bl[D_HID * D_HID];          // W2^T lo
__device__ float g_aggx[N_NODES * D_IN];
__device__ float g_dinv[N_NODES];
__device__ int   g_deg[N_NODES];        // zero at entry (static init + self-reset in scan1)
__device__ int   g_rowptr[N_NODES + 1];
__device__ int   g_cursor[N_NODES];
__device__ __align__(8) long long g_cw[N_EDGES];   // packed {int col, float wt}
__device__ int   g_bsum[256];
__device__ int   g_boff[256];
__device__ int   g_gptr[N_GRAPHS + 1];

__device__ __forceinline__ float selu_f(float x) {
    const float scale = 1.0507009873554805f;
    const float alpha = 1.6732632423543772f;
    return x > 0.f ? scale * x : scale * alpha * (expf(x) - 1.f);
}

__device__ __forceinline__ uint32_t smem_u32(const void* p) {
    uint32_t a;
    asm("{ .reg .u64 t; cvta.to.shared.u64 t, %1; cvt.u32.u64 %0, t; }" : "=r"(a) : "l"(p));
    return a;
}
__device__ __forceinline__ void ldsm4(uint32_t* r, uint32_t addr) {
    asm volatile("ldmatrix.sync.aligned.m8n8.x4.shared.b16 {%0,%1,%2,%3}, [%4];"
                 : "=r"(r[0]), "=r"(r[1]), "=r"(r[2]), "=r"(r[3]) : "r"(addr));
}
__device__ __forceinline__ void mma16816(float* d, const uint32_t* a, uint32_t b0, uint32_t b1) {
    asm volatile(
        "mma.sync.aligned.m16n8k16.row.col.f32.bf16.bf16.f32 "
        "{%0,%1,%2,%3}, {%4,%5,%6,%7}, {%8,%9}, {%0,%1,%2,%3};"
        : "+f"(d[0]), "+f"(d[1]), "+f"(d[2]), "+f"(d[3])
        : "r"(a[0]), "r"(a[1]), "r"(a[2]), "r"(a[3]), "r"(b0), "r"(b1));
}
__device__ __forceinline__ void cp16(uint32_t dst, const void* src) {
    asm volatile("cp.async.cg.shared.global [%0], [%1], 16;" :: "r"(dst), "l"(src));
}
__device__ __forceinline__ void cp_commit() {
    asm volatile("cp.async.commit_group;" ::: "memory");
}
template <int N> __device__ __forceinline__ void cp_wait() {
    asm volatile("cp.async.wait_group %0;" :: "n"(N) : "memory");
}
// load 4 halves (8B) -> float4
__device__ __forceinline__ float4 ldh4(const __half* p) {
    uint2 u = *(const uint2*)p;
    float2 fa = __half22float2(*(__half2*)&u.x);
    float2 fb = __half22float2(*(__half2*)&u.y);
    return make_float4(fa.x, fa.y, fb.x, fb.y);
}

// ======================= CSR build =======================
__global__ void k_hist_edges(const int* __restrict__ ei) {
    int e = blockIdx.x * blockDim.x + threadIdx.x;
    if (e < N_EDGES) atomicAdd(&g_deg[ei[N_EDGES + e]], 1);
}

// block scan of degrees; also: dinv, and self-reset deg for next call
__global__ void k_scan1() {
    __shared__ int wsum[8];
    int b = blockIdx.x, t = threadIdx.x, lane = t & 31, w = t >> 5;
    int i = b * 256 + t;
    int v = 0;
    if (i < N_NODES) {
        v = g_deg[i];
        g_deg[i] = 0;
        g_dinv[i] = rsqrtf((float)(v + 1));    // +1 self loop
    }
    int x = v;
    #pragma unroll
    for (int o = 1; o < 32; o <<= 1) {
        int tv = __shfl_up_sync(0xffffffffu, x, o);
        if (lane >= o) x += tv;
    }
    if (lane == 31) wsum[w] = x;
    __syncthreads();
    if (w == 0) {
        int s = (lane < 8) ? wsum[lane] : 0;
        #pragma unroll
        for (int o = 1; o < 8; o <<= 1) {
            int tv = __shfl_up_sync(0xffffffffu, s, o);
            if (lane >= o) s += tv;
        }
        if (lane < 8) wsum[lane] = s;
    }
    __syncthreads();
    int offs = (w > 0) ? wsum[w - 1] : 0;
    if (i < N_NODES) g_rowptr[i] = x - v + offs;
    if (t == 0) g_bsum[b] = wsum[7];
}

__global__ void k_scan2() {
    __shared__ int wsum[8];
    int t = threadIdx.x, lane = t & 31, w = t >> 5;
    int v = (t < SCAN_BLOCKS) ? g_bsum[t] : 0;
    int x = v;
    #pragma unroll
    for (int o = 1; o < 32; o <<= 1) {
        int tv = __shfl_up_sync(0xffffffffu, x, o);
        if (lane >= o) x += tv;
    }
    if (lane == 31) wsum[w] = x;
    __syncthreads();
    if (w == 0) {
        int s = (lane < 8) ? wsum[lane] : 0;
        #pragma unroll
        for (int o = 1; o < 8; o <<= 1) {
            int tv = __shfl_up_sync(0xffffffffu, s, o);
            if (lane >= o) s += tv;
        }
        if (lane < 8) wsum[lane] = s;
    }
    __syncthreads();
    int offs = (w > 0) ? wsum[w - 1] : 0;
    g_boff[t] = x - v + offs;
    if (t == 0) g_rowptr[N_NODES] = N_EDGES;
}

// rowptr finalize + cursor init + graph-pointer boundary detection (batch is sorted)
__global__ void k_scan3(const int* __restrict__ batch) {
    int i = blockIdx.x * blockDim.x + threadIdx.x;
    if (i < N_NODES) {
        int r = g_rowptr[i] + g_boff[i >> 8];
        g_rowptr[i] = r;
        g_cursor[i] = r;
        int b = batch[i];
        int prev = (i == 0) ? -1 : batch[i - 1];
        for (int g = prev + 1; g <= b; g++) g_gptr[g] = i;
        if (i == N_NODES - 1)
            for (int g = b + 1; g <= N_GRAPHS; g++) g_gptr[g] = N_NODES;
    }
}

// fill CSR: packed {col, wt} single 8B scatter per edge
__global__ void k_fill(const int* __restrict__ ei) {
    int e = blockIdx.x * blockDim.x + threadIdx.x;
    if (e < N_EDGES) {
        int s = ei[e];
        int d = ei[N_EDGES + e];
        int p = atomicAdd(&g_cursor[d], 1);
        float w = g_dinv[s] * g_dinv[d];
        long long pk = (long long)(unsigned int)s |
                       ((long long)(unsigned int)__float_as_int(w) << 32);
        g_cw[p] = pk;
    }
}

// ---- layer-1 aggregation on RAW 14-dim input (agg commutes with W1) ----
__global__ void k_agg14(const float* __restrict__ x) {
    int warp = (blockIdx.x * blockDim.x + threadIdx.x) >> 5;
    int lane = threadIdx.x & 31;
    if (warp >= N_NODES) return;
    int n = warp;
    int half = lane >> 4;
    int f = lane & 15;
    float acc = 0.f;
    int e0 = g_rowptr[n], e1 = g_rowptr[n + 1];
    for (int i = e0 + half; i < e1; i += 2) {
        long long pk = __ldg(&g_cw[i]);
        int s = (int)(unsigned int)pk;
        float w = __int_as_float((int)(pk >> 32));
        if (f < D_IN) acc += x[(size_t)s * D_IN + f] * w;
    }
    if (half == 0 && f < D_IN) {
        float dn = g_dinv[n];
        acc += x[(size_t)n * D_IN + f] * dn * dn;
    }
    acc += __shfl_down_sync(0xffffffffu, acc, 16);
    if (half == 0 && f < D_IN) g_aggx[(size_t)n * D_IN + f] = acc;
}

// ---- layer-1 transform (blocks < LIN1_BLOCKS) + W2 split / A pad (blocks >=) ----
__global__ void k_lin1(const float* __restrict__ W1, const float* __restrict__ b1,
                       const float* __restrict__ W2) {
    int blk = blockIdx.x, tid = threadIdx.x;
    if (blk >= LIN1_BLOCKS) {
        int mb = blk - LIN1_BLOCKS;
        if (mb < 256) {
            int i = mb * 256 + tid;        // 65536
            int k = i >> 8, n = i & 255;
            float w = W2[i];
            __nv_bfloat16 wh = __float2bfloat16(w);
            float rem = w - __bfloat162float(wh);
            g_Bh[n * D_HID + k] = wh;
            g_Bl[n * D_HID + k] = __float2bfloat16(rem);
        } else {
            int i = (mb - 256) * 256 + tid;    // 48*256
            int r = N_NODES + (i >> 8), c = i & 255;
            g_Ah[(size_t)r * D_HID + c] = __float2bfloat16(0.f);
            g_Al[(size_t)r * D_HID + c] = __float2bfloat16(0.f);
        }
        return;
    }
    __shared__ float sW[D_IN * D_HID];
    __shared__ float sx[16 * D_IN];
    for (int i = tid; i < D_IN * D_HID; i += 256) sW[i] = W1[i];
    float bb = b1[tid];
    int n0 = blk * 16;
    int cnt = min(16, N_NODES - n0);
    for (int i = tid; i < cnt * D_IN; i += 256) sx[i] = g_aggx[(size_t)n0 * D_IN + i];
    __syncthreads();
    for (int r = 0; r < cnt; r++) {
        float acc = bb;
        #pragma unroll
        for (int k = 0; k < D_IN; k++) acc += sx[r * D_IN + k] * sW[k * D_HID + tid];
        float h = selu_f(acc);
        __nv_bfloat16 hh = __float2bfloat16(h);
        float rem = h - __bfloat162float(hh);
        size_t idx = (size_t)(n0 + r) * D_HID + tid;
        g_Ah[idx] = hh;
        g_Al[idx] = __float2bfloat16(rem);
    }
}

// ======================= split-bf16 HMMA GEMM (3-stage cp.async ring, dyn smem) =======
// Logical K=768: [0,256)=Ah*Bh, [256,512)=Al*Bh, [512,768)=Ah*Bl; fp16 output
__global__ void __launch_bounds__(256, 2) k_mma() {
    extern __shared__ __align__(16) char dyn[];
    int tid = threadIdx.x;
    int lane = tid & 31, wid = tid >> 5;
    int warp_m = wid >> 2, warp_n = wid & 3;    // 2 x 4 warps, warp tile 64x32
    int bm = blockIdx.x * 128;
    int bn = blockIdx.y * 128;

    float acc[4][4][4];
    #pragma unroll
    for (int i = 0; i < 4; i++)
        #pragma unroll
        for (int j = 0; j < 4; j++)
            #pragma unroll
            for (int k = 0; k < 4; k++) acc[i][j][k] = 0.f;

    int lrow = tid >> 1;            // 0..127
    int lc4  = (tid & 1) * 2;       // uint4 index within 32-elem row chunk

    uint32_t base = smem_u32(dyn);
    uint32_t aB[3] = { base,                       base + MMA_STAGE_BYTES,
                       base + 2 * MMA_STAGE_BYTES };
    uint32_t bB[3] = { base + 3 * MMA_STAGE_BYTES, base + 4 * MMA_STAGE_BYTES,
                       base + 5 * MMA_STAGE_BYTES };
    int tmat = lane >> 3, trow = lane & 7;

    auto src_of = [&](int ch, const __nv_bfloat16*& Asrc, const __nv_bfloat16*& Bsrc) {
        int kg = ch * 32;
        if (kg < 256)      { Asrc = g_Ah + kg;         Bsrc = g_Bh + kg; }
        else if (kg < 512) { Asrc = g_Al + (kg - 256); Bsrc = g_Bh + (kg - 256); }
        else               { Asrc = g_Ah + (kg - 512); Bsrc = g_Bl + (kg - 512); }
    };
    auto issue = [&](int ch, int buf) {
        const __nv_bfloat16 *Asrc, *Bsrc;
        src_of(ch, Asrc, Bsrc);
        const uint4* ap = (const uint4*)(Asrc + (size_t)(bm + lrow) * D_HID);
        const uint4* bp = (const uint4*)(Bsrc + (size_t)(bn + lrow) * D_HID);
        uint32_t ad = aB[buf] + (lrow * 40 + lc4 * 8) * 2;
        uint32_t bd = bB[buf] + (lrow * 40 + lc4 * 8) * 2;
        cp16(ad,      ap + lc4);
        cp16(ad + 16, ap + lc4 + 1);
        cp16(bd,      bp + lc4);
        cp16(bd + 16, bp + lc4 + 1);
        cp_commit();
    };

    issue(0, 0);
    issue(1, 1);
    for (int ch = 0; ch < 24; ch++) {
        int cur = ch % 3;
        if (ch + 2 < 24) {
            issue(ch + 2, (ch + 2) % 3);
            cp_wait<2>();
        } else if (ch + 1 < 24) {
            cp_wait<1>();
        } else {
            cp_wait<0>();
        }
        __syncthreads();
        #pragma unroll
        for (int ks = 0; ks < 2; ks++) {
            uint32_t a[4][4], b[2][4];
            #pragma unroll
            for (int mt = 0; mt < 4; mt++) {
                int row = warp_m * 64 + mt * 16 + trow + (tmat & 1) * 8;
                int col = ks * 16 + (tmat >> 1) * 8;
                ldsm4(a[mt], aB[cur] + (row * 40 + col) * 2);
            }
            #pragma unroll
            for (int np = 0; np < 2; np++) {
                int row = warp_n * 32 + np * 16 + trow + (tmat >> 1) * 8;
                int col = ks * 16 + (tmat & 1) * 8;
                ldsm4(b[np], bB[cur] + (row * 40 + col) * 2);
            }
            #pragma unroll
            for (int mt = 0; mt < 4; mt++)
                #pragma unroll
                for (int nt = 0; nt < 4; nt++)
                    mma16816(acc[mt][nt], a[mt],
                             b[nt >> 1][(nt & 1) * 2], b[nt >> 1][(nt & 1) * 2 + 1]);
        }
        __syncthreads();
    }

    // epilogue: fp16 stores (consumed only by the aggregation gather)
    int gid = lane >> 2, tig = lane & 3;
    #pragma unroll
    for (int mt = 0; mt < 4; mt++) {
        #pragma unroll
        for (int nt = 0; nt < 4; nt++) {
            int r0 = bm + warp_m * 64 + mt * 16 + gid;
            int c  = bn + warp_n * 32 + nt * 8 + tig * 2;
            if (r0 < N_NODES)
                *(__half2*)&g_h2[(size_t)r0 * D_HID + c] =
                    __floats2half2_rn(acc[mt][nt][0], acc[mt][nt][1]);
            int r1 = r0 + 8;
            if (r1 < N_NODES)
                *(__half2*)&g_h2[(size_t)r1 * D_HID + c] =
                    __floats2half2_rn(acc[mt][nt][2], acc[mt][nt][3]);
        }
    }
}

// ---- layer-2 aggregation: g_bufA[n] = selu( agg(g_h2) + b2 ) ----
// 128 threads = 2 nodes x 64 threads; fp16 gathers (8B per thread-row), fp32 accum
__global__ void k_aggregate(const float* __restrict__ bias) {
    int tid = threadIdx.x;
    int n = blockIdx.x * 2 + (tid >> 6);
    int f = (tid & 63) * 4;
    if (n >= N_NODES) return;
    float dn = g_dinv[n];
    float sw = dn * dn;
    float4 sv = ldh4(&g_h2[(size_t)n * D_HID + f]);
    float4 accA = make_float4(sv.x * sw, sv.y * sw, sv.z * sw, sv.w * sw);
    float4 accB = make_float4(0.f, 0.f, 0.f, 0.f);
    int i = g_rowptr[n], e1 = g_rowptr[n + 1];
    for (; i + 4 <= e1; i += 4) {
        long long p0 = __ldg(&g_cw[i]);
        long long p1 = __ldg(&g_cw[i + 1]);
        long long p2 = __ldg(&g_cw[i + 2]);
        long long p3 = __ldg(&g_cw[i + 3]);
        int s0 = (int)(unsigned int)p0; float w0 = __int_as_float((int)(p0 >> 32));
        int s1 = (int)(unsigned int)p1; float w1 = __int_as_float((int)(p1 >> 32));
        int s2 = (int)(unsigned int)p2; float w2 = __int_as_float((int)(p2 >> 32));
        int s3 = (int)(unsigned int)p3; float w3 = __int_as_float((int)(p3 >> 32));
        float4 v0 = ldh4(&g_h2[(size_t)s0 * D_HID + f]);
        float4 v1 = ldh4(&g_h2[(size_t)s1 * D_HID + f]);
        float4 v2 = ldh4(&g_h2[(size_t)s2 * D_HID + f]);
        float4 v3 = ldh4(&g_h2[(size_t)s3 * D_HID + f]);
        accA.x += v0.x * w0; accA.y += v0.y * w0; accA.z += v0.z * w0; accA.w += v0.w * w0;
        accB.x += v1.x * w1; accB.y += v1.y * w1; accB.z += v1.z * w1; accB.w += v1.w * w1;
        accA.x += v2.x * w2; accA.y += v2.y * w2; accA.z += v2.z * w2; accA.w += v2.w * w2;
        accB.x += v3.x * w3; accB.y += v3.y * w3; accB.z += v3.z * w3; accB.w += v3.w * w3;
    }
    for (; i < e1; i++) {
        long long pk = __ldg(&g_cw[i]);
        int s = (int)(unsigned int)pk;
        float w = __int_as_float((int)(pk >> 32));
        float4 v = ldh4(&g_h2[(size_t)s * D_HID + f]);
        accA.x += v.x * w; accA.y += v.y * w; accA.z += v.z * w; accA.w += v.w * w;
    }
    const float4 bb = *(const float4*)&bias[f];
    float4 o;
    o.x = selu_f(accA.x + accB.x + bb.x);
    o.y = selu_f(accA.y + accB.y + bb.y);
    o.z = selu_f(accA.z + accB.z + bb.z);
    o.w = selu_f(accA.w + accB.w + bb.w);
    *(float4*)&g_bufA[(size_t)n * D_HID + f] = o;
}

// ---- fused head ----
__global__ void k_head(const float* __restrict__ fc1w, const float* __restrict__ fc1b,
                       const float* __restrict__ fc2w, const float* __restrict__ fc2b,
                       float* __restrict__ out) {
    __shared__ float sp[D_HID];
    __shared__ float h1[128];
    __shared__ float sl[2];
    int g = blockIdx.x, tid = threadIdx.x;
    int s = g_gptr[g], e = g_gptr[g + 1];
    float acc = 0.f;
    int n = s;
    for (; n + 4 <= e; n += 4) {
        float v0 = g_bufA[(size_t)(n + 0) * D_HID + tid];
        float v1 = g_bufA[(size_t)(n + 1) * D_HID + tid];
        float v2 = g_bufA[(size_t)(n + 2) * D_HID + tid];
        float v3 = g_bufA[(size_t)(n + 3) * D_HID + tid];
        acc += (v0 + v1) + (v2 + v3);
    }
    for (; n < e; n++) acc += g_bufA[(size_t)n * D_HID + tid];
    float c = fmaxf((float)(e - s), 1.f);
    sp[tid] = selu_f(acc / c);
    __syncthreads();
    if (tid < 128) {
        float a = fc1b[tid];
        #pragma unroll 8
        for (int k = 0; k < D_HID; k++) a += sp[k] * fc1w[k * 128 + tid];
        h1[tid] = selu_f(a);
    }
    __syncthreads();
    if (tid < 64) {
        int cc = tid >> 5, lane = tid & 31;
        float p = 0.f;
        for (int k = lane; k < 128; k += 32) p += h1[k] * fc2w[k * 2 + cc];
        #pragma unroll
        for (int o = 16; o; o >>= 1) p += __shfl_down_sync(0xffffffffu, p, o);
        if (lane == 0) sl[cc] = p + fc2b[cc];
    }
    __syncthreads();
    if (tid < 2) {
        float l0 = sl[0], l1 = sl[1];
        float m = fmaxf(l0, l1);
        float lse = m + logf(expf(l0 - m) + expf(l1 - m));
        out[g * 2 + tid] = sl[tid] - lse;
    }
}

extern "C" void kernel_launch(void* const* d_in, const int* in_sizes, int n_in,
                              void* d_out, int out_size) {
    const float* x     = (const float*)d_in[0];
    const int*   ei    = (const int*)d_in[1];
    const int*   batch = (const int*)d_in[2];
    const float* W1    = (const float*)d_in[3];
    const float* b1    = (const float*)d_in[4];
    const float* W2    = (const float*)d_in[5];
    const float* b2    = (const float*)d_in[6];
    const float* fc1w  = (const float*)d_in[7];
    const float* fc1b  = (const float*)d_in[8];
    const float* fc2w  = (const float*)d_in[9];
    const float* fc2b  = (const float*)d_in[10];
    float* out = (float*)d_out;

    cudaFuncSetAttribute(k_mma, cudaFuncAttributeMaxDynamicSharedMemorySize, MMA_SMEM_BYTES);

    // CSR + normalization build (g_deg is zero at entry: static init + scan1 self-reset)
    k_hist_edges<<<(N_EDGES + 255) / 256, 256>>>(ei);
    k_scan1<<<SCAN_BLOCKS, 256>>>();
    k_scan2<<<1, 256>>>();
    k_scan3<<<(N_NODES + 255) / 256, 256>>>(batch);
    k_fill<<<(N_EDGES + 255) / 256, 256>>>(ei);

    // layer 1: aggregate raw input, transform + bf16 hi/lo split (+ fused W2 split/pad)
    k_agg14<<<(N_NODES * 32 + 127) / 128, 128>>>(x);
    k_lin1<<<LIN1_BLOCKS + MISC_BLOCKS, 256>>>(W1, b1, W2);

    // layer 2: HMMA split-bf16 GEMM -> fp16, then fp16-gather aggregate (+bias+selu)
    dim3 gmma(N_PAD / 128, 2);
    k_mma<<<gmma, 256, MMA_SMEM_BYTES>>>();
    k_aggregate<<<N_NODES / 2, 128>>>(b2);

    // head
    k_head<<<N_GRAPHS, 256>>>(fc1w, fc1b, fc2w, fc2b, out);
}